// round 9
// baseline (speedup 1.0000x reference)
#include <cuda_runtime.h>
#include <cstdint>

// ---------------------------------------------------------------------------
// YOLO post-processing: conf filter -> per-class scatter -> per-class in-warp
// sort (register bitonic on (score,idx) keys) -> per-class greedy NMS entirely
// in registers -> hybrid register/shfl/smem bitonic of kept confidences ->
// "person present" gate.
//
// Counters are self-restoring (zeroed by their consumer) so no init kernel.
//
// detections f32 [8, 10647, 85] -> out f32 [8, 4096]
// ---------------------------------------------------------------------------

#define BATCH   8
#define NDET    10647
#define NCH     85
#define NCLS    80
#define TOPK    4096
#define CONF_T  0.8f
#define NMS_T   0.4f
#define MAXC    128               // per-class cap (binomial mean 26.6, sd 5.1 -> 20 sigma)
#define RPB     128               // rows per block in k_score
#define TPB     512               // threads per block in k_score (4 per row)

// ------------------------- device scratch (static) -------------------------
// (zero-initialized at module load; consumers restore counters to 0 each run)
__device__ float              g_cc_all[BATCH][NDET];
__device__ unsigned           g_ccnt[BATCH][NCLS];
__device__ unsigned long long g_cls[BATCH][NCLS][MAXC];   // (score_bits<<32)|(~idx)
__device__ float              g_kept[BATCH][TOPK];
__device__ unsigned           g_kcnt[BATCH];
__device__ int                g_isok[BATCH];

// ------------- kernel 1: scores (smem-staged, 4 threads per row) -----------
// Block stages RPB rows (RPB*85 floats) via float4 streaming loads with 512
// threads (100% occ at 4 blocks/SM), then 4 threads per row scan 20-class
// segments from smem and combine via 2-step shfl_xor (exact first-occurrence
// argmax semantics).
__global__ void __launch_bounds__(TPB, 4) k_score(const float* __restrict__ det) {
    __shared__ float sm[RPB * NCH];        // 43,520 B

    int t     = threadIdx.x;
    int row0  = blockIdx.x * RPB;
    int total = BATCH * NDET;
    int rows  = total - row0; if (rows > RPB) rows = RPB;

    // chunk is float4-exact: row0*85 and rows*85 are multiples of 4,
    // base byte offset is a multiple of 16.
    int nvec = (rows * NCH) >> 2;
    const float4* src = (const float4*)(det + (size_t)row0 * NCH);
    float4* dst = (float4*)sm;
    for (int i = t; i < nvec; i += TPB) dst[i] = src[i];
    __syncthreads();

    int row = t >> 2;          // 0..127
    int seg = t & 3;           // 0..3 -> classes [seg*20, seg*20+20)
    bool act = (row < rows);
    const float* r = &sm[row * NCH];

    // segment argmax (strict > keeps first occurrence within segment)
    float bv = -3.0e38f;
    int   bi = 1 << 30;
    if (act) {
        int c0 = seg * 20;
        bv = r[5 + c0]; bi = c0;
#pragma unroll 5
        for (int i = 1; i < 20; ++i) {
            float v = r[5 + c0 + i];
            if (v > bv) { bv = v; bi = c0 + i; }
        }
    }

    // combine across the 4 segment lanes (same row -> same activity)
#pragma unroll
    for (int off = 1; off <= 2; off <<= 1) {
        float ov = __shfl_xor_sync(0xffffffffu, bv, off);
        int   oi = __shfl_xor_sync(0xffffffffu, bi, off);
        if (ov > bv || (ov == bv && oi < bi)) { bv = ov; bi = oi; }
    }

    if (act && seg == 0) {
        int gw = row0 + row;
        int b  = gw / NDET;
        int n  = gw - b * NDET;
        float obj = r[4];
        g_cc_all[b][n] = bv;
        if (obj >= CONF_T) {
            float score = __fmul_rn(obj, bv);             // > 0 always here
            unsigned pos = atomicAdd(&g_ccnt[b][bi], 1u);
            if (pos < MAXC) {
                g_cls[b][bi][pos] =
                    ((unsigned long long)__float_as_uint(score) << 32) |
                    (unsigned long long)(0xFFFFFFFFu - (unsigned)n);
            }
        }
    }
}

// ------------------ warp bitonic sort, descending, S*32 keys ----------------
template<int S>
__device__ __forceinline__ void warp_sort_desc(unsigned long long (&key)[S], int lane) {
    const int N = S * 32;
    for (int k = 2; k <= N; k <<= 1) {
        for (int j = k >> 1; j > 0; j >>= 1) {
            if (j >= 32) {
                int sj = j >> 5;
#pragma unroll
                for (int s = 0; s < S; ++s) {
                    int ps = s ^ sj;
                    if (ps > s) {
                        bool desc = (((s * 32 + lane) & k) == 0);
                        unsigned long long a = key[s], c = key[ps];
                        if (desc ? (a < c) : (a > c)) { key[s] = c; key[ps] = a; }
                    }
                }
            } else {
#pragma unroll
                for (int s = 0; s < S; ++s) {
                    unsigned long long o = __shfl_xor_sync(0xffffffffu, key[s], j);
                    bool desc  = (((s * 32 + lane) & k) == 0);
                    bool lower = ((lane & j) == 0);
                    unsigned long long mx = key[s] > o ? key[s] : o;
                    unsigned long long mn = key[s] > o ? o : key[s];
                    key[s] = (desc == lower) ? mx : mn;
                }
            }
        }
    }
}

// -------------------- per-class greedy NMS (register resident) --------------
template<int S>
__device__ __forceinline__ void nms_class(const float* __restrict__ det,
                                          int b, int c, int m, int lane,
                                          bool* personOut) {
    // load + sort keys
    unsigned long long key[S];
#pragma unroll
    for (int s = 0; s < S; ++s) {
        int e = s * 32 + lane;
        key[s] = (e < m) ? g_cls[b][c][e] : 0ULL;
    }
    warp_sort_desc<S>(key, lane);

    // decode idx, load boxes into registers (element e = s*32+lane)
    unsigned idx[S];
    float x1[S], y1[S], x2[S], y2[S], ar[S];
#pragma unroll
    for (int s = 0; s < S; ++s) {
        int e = s * 32 + lane;
        if (e < m) {
            unsigned n = 0xFFFFFFFFu - (unsigned)(key[s] & 0xFFFFFFFFull);
            idx[s] = n;
            const float* row = det + ((size_t)b * NDET + (size_t)n) * NCH;
            float x = row[0], y = row[1], w = row[2], h = row[3];
            float hw = __fmul_rn(w, 0.5f);
            float hh = __fmul_rn(h, 0.5f);
            x1[s] = __fsub_rn(x, hw); y1[s] = __fsub_rn(y, hh);
            x2[s] = __fadd_rn(x, hw); y2[s] = __fadd_rn(y, hh);
            ar[s] = __fmul_rn(__fadd_rn(__fsub_rn(x2[s], x1[s]), 1.0f),
                              __fadd_rn(__fsub_rn(y2[s], y1[s]), 1.0f));
        }
    }

    // alive bitmask, replicated on every lane
    unsigned alive[S];
#pragma unroll
    for (int s = 0; s < S; ++s) {
        int cnt = m - s * 32;
        if (cnt < 0) cnt = 0; if (cnt > 32) cnt = 32;
        alive[s] = (cnt == 32) ? 0xFFFFFFFFu : ((1u << cnt) - 1u);
    }

    // greedy: serial over rank order; suppressed rows never suppress
#pragma unroll
    for (int si = 0; si < S; ++si) {
        for (int ii = 0; ii < 32; ++ii) {
            int i = si * 32 + ii;
            if (i >= m) break;                         // uniform
            if (!((alive[si] >> ii) & 1u)) continue;   // uniform (replicated)
            float bx1 = __shfl_sync(0xffffffffu, x1[si], ii);
            float by1 = __shfl_sync(0xffffffffu, y1[si], ii);
            float bx2 = __shfl_sync(0xffffffffu, x2[si], ii);
            float by2 = __shfl_sync(0xffffffffu, y2[si], ii);
            float bar = __shfl_sync(0xffffffffu, ar[si], ii);
#pragma unroll
            for (int sj = si; sj < S; ++sj) {
                int e = sj * 32 + lane;
                bool kill = false;
                if (e > i && e < m && ((alive[sj] >> lane) & 1u)) {
                    float iw = fmaxf(__fadd_rn(__fsub_rn(fminf(bx2, x2[sj]), fmaxf(bx1, x1[sj])), 1.0f), 0.0f);
                    float ih = fmaxf(__fadd_rn(__fsub_rn(fminf(by2, y2[sj]), fmaxf(by1, y1[sj])), 1.0f), 0.0f);
                    float inter = __fmul_rn(iw, ih);
                    float denom = __fadd_rn(__fsub_rn(__fadd_rn(bar, ar[sj]), inter), 1e-16f);
                    kill = (__fdiv_rn(inter, denom) > NMS_T);
                }
                unsigned km = __ballot_sync(0xffffffffu, kill);
                alive[sj] &= ~km;
            }
        }
    }

    // emit kept confidences (order-free; sorted later)
    bool person = false;
#pragma unroll
    for (int s = 0; s < S; ++s) {
        int e = s * 32 + lane;
        if (e < m && ((alive[s] >> lane) & 1u)) {
            float cc = g_cc_all[b][idx[s]];
            unsigned pos = atomicAdd(&g_kcnt[b], 1u);
            if (pos < TOPK) g_kept[b][pos] = cc;
            person = true;
        }
    }
    *personOut = person;
}

// ----------- kernel 2: per-class NMS, 1 warp per (image, class) -------------
__global__ void __launch_bounds__(256) k_nms(const float* __restrict__ det) {
    int w    = threadIdx.x >> 5;
    int lane = threadIdx.x & 31;
    int b    = blockIdx.x / 10;
    int c    = (blockIdx.x - b * 10) * 8 + w;    // 0..79

    int m = (int)g_ccnt[b][c];
    __syncwarp();
    if (lane == 0) g_ccnt[b][c] = 0u;            // self-restore for next run
    if (m > MAXC) m = MAXC;

    bool person = false;
    if (m > 0) {
        if (m <= 32)      nms_class<1>(det, b, c, m, lane, &person);
        else if (m <= 64) nms_class<2>(det, b, c, m, lane, &person);
        else              nms_class<4>(det, b, c, m, lane, &person);
    }
    if (c == 0) {
        unsigned any = __ballot_sync(0xffffffffu, person);
        if (lane == 0) g_isok[b] = (any != 0u) ? 1 : 0;
    }
}

// ------- kernel 3: hybrid register/shfl/smem bitonic sort of kept confs -----
// E elements per thread (index = t + s*1024). Stages:
//   j >= 1024 : intra-thread register exchange
//   32<=j<=512: smem exchange (2 barriers)
//   j <= 16   : shfl_xor, barrier-free
template<int E>
__device__ __forceinline__ void sort_desc_emit(float* __restrict__ out, float* sm,
                                               int b, int K, float scale) {
    const int N = E * 1024;
    int t = threadIdx.x;
    float r[E];
#pragma unroll
    for (int s = 0; s < E; ++s) {
        int e = t + s * 1024;
        r[s] = (e < K) ? g_kept[b][e] : 0.0f;
    }

    for (int k = 2; k <= N; k <<= 1) {
        for (int j = k >> 1; j > 0; j >>= 1) {
            if (j >= 1024) {
                int d = j >> 10;
#pragma unroll
                for (int s = 0; s < E; ++s) {
                    if (!(s & d) && (s ^ d) < E) {
                        int i = t + s * 1024;
                        bool desc = ((i & k) == 0);
                        float a = r[s], c = r[s ^ d];
                        float mx = fmaxf(a, c), mn = fminf(a, c);
                        r[s]     = desc ? mx : mn;
                        r[s ^ d] = desc ? mn : mx;
                    }
                }
            } else if (j >= 32) {
                __syncthreads();
#pragma unroll
                for (int s = 0; s < E; ++s) sm[t + s * 1024] = r[s];
                __syncthreads();
#pragma unroll
                for (int s = 0; s < E; ++s) {
                    int i = t + s * 1024;
                    float p = sm[i ^ j];
                    bool keepMax = (((i & k) == 0) == ((i & j) == 0));
                    r[s] = keepMax ? fmaxf(r[s], p) : fminf(r[s], p);
                }
            } else {
#pragma unroll
                for (int s = 0; s < E; ++s) {
                    float p = __shfl_xor_sync(0xffffffffu, r[s], j);
                    int i = t + s * 1024;
                    bool keepMax = (((i & k) == 0) == ((i & j) == 0));
                    r[s] = keepMax ? fmaxf(r[s], p) : fminf(r[s], p);
                }
            }
        }
    }

#pragma unroll
    for (int s = 0; s < E; ++s) {
        int i = t + s * 1024;
        out[(size_t)b * TOPK + i] = __fmul_rn(r[s], scale);
    }
    for (int i = N + t; i < TOPK; i += 1024)
        out[(size_t)b * TOPK + i] = 0.0f;
}

__global__ void __launch_bounds__(1024) k_final(float* __restrict__ out) {
    __shared__ float sm[TOPK];   // 16 KB
    int b = blockIdx.x;

    int K = (int)g_kcnt[b];
    if (K > TOPK) K = TOPK;
    float scale = g_isok[b] ? 1.0f : 0.0f;
    __syncthreads();                              // everyone has read g_kcnt
    if (threadIdx.x == 0) g_kcnt[b] = 0u;         // self-restore for next run

    if (K <= 1024)      sort_desc_emit<1>(out, sm, b, K, scale);
    else if (K <= 2048) sort_desc_emit<2>(out, sm, b, K, scale);
    else                sort_desc_emit<4>(out, sm, b, K, scale);
}

// --------------------------------- launch ----------------------------------
extern "C" void kernel_launch(void* const* d_in, const int* in_sizes, int n_in,
                              void* d_out, int out_size) {
    (void)in_sizes; (void)n_in; (void)out_size;
    const float* det = (const float*)d_in[0];
    float* out = (float*)d_out;

    k_score<<<(BATCH * NDET + RPB - 1) / RPB, TPB>>>(det);  // 128 rows, 512 thr
    k_nms<<<BATCH * 10, 256>>>(det);                        // 1 warp per (image, class)
    k_final<<<BATCH, 1024>>>(out);
}

// round 10
// speedup vs baseline: 1.0954x; 1.0954x over previous
#include <cuda_runtime.h>
#include <cstdint>

// ---------------------------------------------------------------------------
// YOLO post-processing: conf filter -> per-class scatter -> per-class in-warp
// sort (register bitonic on (score,idx) keys) -> per-class greedy NMS entirely
// in registers -> hybrid register/shfl/smem bitonic of kept confidences ->
// "person present" gate.
//
// k_score stages row tiles via one TMA bulk copy per block (no per-thread
// load issue), then 2 threads/row scan 40-class segments from smem.
//
// detections f32 [8, 10647, 85] -> out f32 [8, 4096]
// ---------------------------------------------------------------------------

#define BATCH   8
#define NDET    10647
#define NCH     85
#define NCLS    80
#define TOPK    4096
#define CONF_T  0.8f
#define NMS_T   0.4f
#define MAXC    128               // per-class cap (binomial mean 26.6, sd 5.1 -> 20 sigma)
#define RPB     128               // rows per block in k_score
#define TPB     256               // threads per block in k_score (2 per row)

// ------------------------- device scratch (static) -------------------------
// (zero-initialized at module load; consumers restore counters to 0 each run)
__device__ float              g_cc_all[BATCH][NDET];
__device__ unsigned           g_ccnt[BATCH][NCLS];
__device__ unsigned long long g_cls[BATCH][NCLS][MAXC];   // (score_bits<<32)|(~idx)
__device__ float              g_kept[BATCH][TOPK];
__device__ unsigned           g_kcnt[BATCH];
__device__ int                g_isok[BATCH];

// ------------- kernel 1: scores (TMA-staged, 2 threads per row) ------------
__global__ void __launch_bounds__(TPB) k_score(const float* __restrict__ det) {
    __shared__ __align__(16) float sm[RPB * NCH];          // 43,520 B
    __shared__ __align__(8)  unsigned long long mbar;

    int t     = threadIdx.x;
    int row0  = blockIdx.x * RPB;
    int total = BATCH * NDET;
    int rows  = total - row0; if (rows > RPB) rows = RPB;
    unsigned bytes = (unsigned)(rows * NCH) * 4u;          // multiple of 16

    unsigned mba = (unsigned)__cvta_generic_to_shared(&mbar);
    unsigned sa  = (unsigned)__cvta_generic_to_shared(&sm[0]);

    if (t == 0)
        asm volatile("mbarrier.init.shared.b64 [%0], 1;" :: "r"(mba) : "memory");
    __syncthreads();

    if (t == 0) {
        const float* src = det + (size_t)row0 * NCH;       // 16B-aligned
        asm volatile("mbarrier.arrive.expect_tx.shared.b64 _, [%0], %1;"
                     :: "r"(mba), "r"(bytes) : "memory");
        asm volatile("cp.async.bulk.shared::cluster.global.mbarrier::complete_tx::bytes "
                     "[%0], [%1], %2, [%3];"
                     :: "r"(sa), "l"(src), "r"(bytes), "r"(mba) : "memory");
    }

    // all threads wait for the tile (phase 0; smem barrier fresh each launch)
    {
        unsigned done;
        do {
            asm volatile(
                "{ .reg .pred p;\n"
                "  mbarrier.try_wait.parity.acquire.cta.shared::cta.b64 p, [%1], 0, 0x989680;\n"
                "  selp.b32 %0, 1, 0, p; }"
                : "=r"(done) : "r"(mba) : "memory");
        } while (!done);
    }

    int row = t >> 1;          // 0..127
    int seg = t & 1;           // classes [seg*40, seg*40+40)
    const float* r = &sm[row * NCH];

    // segment argmax (strict > keeps first occurrence within segment)
    int c0 = seg * 40;
    float bv = r[5 + c0];
    int   bi = c0;
#pragma unroll 8
    for (int i = 1; i < 40; ++i) {
        float v = r[5 + c0 + i];
        if (v > bv) { bv = v; bi = c0 + i; }
    }

    // combine the two segment lanes (no early exit before shfl)
    {
        float ov = __shfl_xor_sync(0xffffffffu, bv, 1);
        int   oi = __shfl_xor_sync(0xffffffffu, bi, 1);
        if (ov > bv || (ov == bv && oi < bi)) { bv = ov; bi = oi; }
    }

    if (seg == 0 && row < rows) {
        int gw = row0 + row;
        int b  = gw / NDET;
        int n  = gw - b * NDET;
        float obj = r[4];
        g_cc_all[b][n] = bv;
        if (obj >= CONF_T) {
            float score = __fmul_rn(obj, bv);             // > 0 always here
            unsigned pos = atomicAdd(&g_ccnt[b][bi], 1u);
            if (pos < MAXC) {
                g_cls[b][bi][pos] =
                    ((unsigned long long)__float_as_uint(score) << 32) |
                    (unsigned long long)(0xFFFFFFFFu - (unsigned)n);
            }
        }
    }
}

// ------------------ warp bitonic sort, descending, S*32 keys ----------------
template<int S>
__device__ __forceinline__ void warp_sort_desc(unsigned long long (&key)[S], int lane) {
    const int N = S * 32;
    for (int k = 2; k <= N; k <<= 1) {
        for (int j = k >> 1; j > 0; j >>= 1) {
            if (j >= 32) {
                int sj = j >> 5;
#pragma unroll
                for (int s = 0; s < S; ++s) {
                    int ps = s ^ sj;
                    if (ps > s) {
                        bool desc = (((s * 32 + lane) & k) == 0);
                        unsigned long long a = key[s], c = key[ps];
                        if (desc ? (a < c) : (a > c)) { key[s] = c; key[ps] = a; }
                    }
                }
            } else {
#pragma unroll
                for (int s = 0; s < S; ++s) {
                    unsigned long long o = __shfl_xor_sync(0xffffffffu, key[s], j);
                    bool desc  = (((s * 32 + lane) & k) == 0);
                    bool lower = ((lane & j) == 0);
                    unsigned long long mx = key[s] > o ? key[s] : o;
                    unsigned long long mn = key[s] > o ? o : key[s];
                    key[s] = (desc == lower) ? mx : mn;
                }
            }
        }
    }
}

// -------------------- per-class greedy NMS (register resident) --------------
template<int S>
__device__ __forceinline__ void nms_class(const float* __restrict__ det,
                                          int b, int c, int m, int lane,
                                          bool* personOut) {
    // load + sort keys
    unsigned long long key[S];
#pragma unroll
    for (int s = 0; s < S; ++s) {
        int e = s * 32 + lane;
        key[s] = (e < m) ? g_cls[b][c][e] : 0ULL;
    }
    warp_sort_desc<S>(key, lane);

    // decode idx, load boxes into registers (element e = s*32+lane)
    unsigned idx[S];
    float x1[S], y1[S], x2[S], y2[S], ar[S];
#pragma unroll
    for (int s = 0; s < S; ++s) {
        int e = s * 32 + lane;
        if (e < m) {
            unsigned n = 0xFFFFFFFFu - (unsigned)(key[s] & 0xFFFFFFFFull);
            idx[s] = n;
            const float* row = det + ((size_t)b * NDET + (size_t)n) * NCH;
            float x = row[0], y = row[1], w = row[2], h = row[3];
            float hw = __fmul_rn(w, 0.5f);
            float hh = __fmul_rn(h, 0.5f);
            x1[s] = __fsub_rn(x, hw); y1[s] = __fsub_rn(y, hh);
            x2[s] = __fadd_rn(x, hw); y2[s] = __fadd_rn(y, hh);
            ar[s] = __fmul_rn(__fadd_rn(__fsub_rn(x2[s], x1[s]), 1.0f),
                              __fadd_rn(__fsub_rn(y2[s], y1[s]), 1.0f));
        }
    }

    // alive bitmask, replicated on every lane
    unsigned alive[S];
#pragma unroll
    for (int s = 0; s < S; ++s) {
        int cnt = m - s * 32;
        if (cnt < 0) cnt = 0; if (cnt > 32) cnt = 32;
        alive[s] = (cnt == 32) ? 0xFFFFFFFFu : ((1u << cnt) - 1u);
    }

    // greedy: serial over rank order; suppressed rows never suppress
#pragma unroll
    for (int si = 0; si < S; ++si) {
        for (int ii = 0; ii < 32; ++ii) {
            int i = si * 32 + ii;
            if (i >= m) break;                         // uniform
            if (!((alive[si] >> ii) & 1u)) continue;   // uniform (replicated)
            float bx1 = __shfl_sync(0xffffffffu, x1[si], ii);
            float by1 = __shfl_sync(0xffffffffu, y1[si], ii);
            float bx2 = __shfl_sync(0xffffffffu, x2[si], ii);
            float by2 = __shfl_sync(0xffffffffu, y2[si], ii);
            float bar = __shfl_sync(0xffffffffu, ar[si], ii);
#pragma unroll
            for (int sj = si; sj < S; ++sj) {
                int e = sj * 32 + lane;
                bool kill = false;
                if (e > i && e < m && ((alive[sj] >> lane) & 1u)) {
                    float iw = fmaxf(__fadd_rn(__fsub_rn(fminf(bx2, x2[sj]), fmaxf(bx1, x1[sj])), 1.0f), 0.0f);
                    float ih = fmaxf(__fadd_rn(__fsub_rn(fminf(by2, y2[sj]), fmaxf(by1, y1[sj])), 1.0f), 0.0f);
                    float inter = __fmul_rn(iw, ih);
                    float denom = __fadd_rn(__fsub_rn(__fadd_rn(bar, ar[sj]), inter), 1e-16f);
                    kill = (__fdiv_rn(inter, denom) > NMS_T);
                }
                unsigned km = __ballot_sync(0xffffffffu, kill);
                alive[sj] &= ~km;
            }
        }
    }

    // emit kept confidences (order-free; sorted later)
    bool person = false;
#pragma unroll
    for (int s = 0; s < S; ++s) {
        int e = s * 32 + lane;
        if (e < m && ((alive[s] >> lane) & 1u)) {
            float cc = g_cc_all[b][idx[s]];
            unsigned pos = atomicAdd(&g_kcnt[b], 1u);
            if (pos < TOPK) g_kept[b][pos] = cc;
            person = true;
        }
    }
    *personOut = person;
}

// ----------- kernel 2: per-class NMS, 1 warp per (image, class) -------------
__global__ void __launch_bounds__(256) k_nms(const float* __restrict__ det) {
    int w    = threadIdx.x >> 5;
    int lane = threadIdx.x & 31;
    int b    = blockIdx.x / 10;
    int c    = (blockIdx.x - b * 10) * 8 + w;    // 0..79

    int m = (int)g_ccnt[b][c];
    __syncwarp();
    if (lane == 0) g_ccnt[b][c] = 0u;            // self-restore for next run
    if (m > MAXC) m = MAXC;

    bool person = false;
    if (m > 0) {
        if (m <= 32)      nms_class<1>(det, b, c, m, lane, &person);
        else if (m <= 64) nms_class<2>(det, b, c, m, lane, &person);
        else              nms_class<4>(det, b, c, m, lane, &person);
    }
    if (c == 0) {
        unsigned any = __ballot_sync(0xffffffffu, person);
        if (lane == 0) g_isok[b] = (any != 0u) ? 1 : 0;
    }
}

// ------- kernel 3: hybrid register/shfl/smem bitonic sort of kept confs -----
// E elements per thread (index = t + s*1024). Stages:
//   j >= 1024 : intra-thread register exchange
//   32<=j<=512: smem exchange (2 barriers)
//   j <= 16   : shfl_xor, barrier-free
template<int E>
__device__ __forceinline__ void sort_desc_emit(float* __restrict__ out, float* sm,
                                               int b, int K, float scale) {
    const int N = E * 1024;
    int t = threadIdx.x;
    float r[E];
#pragma unroll
    for (int s = 0; s < E; ++s) {
        int e = t + s * 1024;
        r[s] = (e < K) ? g_kept[b][e] : 0.0f;
    }

    for (int k = 2; k <= N; k <<= 1) {
        for (int j = k >> 1; j > 0; j >>= 1) {
            if (j >= 1024) {
                int d = j >> 10;
#pragma unroll
                for (int s = 0; s < E; ++s) {
                    if (!(s & d) && (s ^ d) < E) {
                        int i = t + s * 1024;
                        bool desc = ((i & k) == 0);
                        float a = r[s], c = r[s ^ d];
                        float mx = fmaxf(a, c), mn = fminf(a, c);
                        r[s]     = desc ? mx : mn;
                        r[s ^ d] = desc ? mn : mx;
                    }
                }
            } else if (j >= 32) {
                __syncthreads();
#pragma unroll
                for (int s = 0; s < E; ++s) sm[t + s * 1024] = r[s];
                __syncthreads();
#pragma unroll
                for (int s = 0; s < E; ++s) {
                    int i = t + s * 1024;
                    float p = sm[i ^ j];
                    bool keepMax = (((i & k) == 0) == ((i & j) == 0));
                    r[s] = keepMax ? fmaxf(r[s], p) : fminf(r[s], p);
                }
            } else {
#pragma unroll
                for (int s = 0; s < E; ++s) {
                    float p = __shfl_xor_sync(0xffffffffu, r[s], j);
                    int i = t + s * 1024;
                    bool keepMax = (((i & k) == 0) == ((i & j) == 0));
                    r[s] = keepMax ? fmaxf(r[s], p) : fminf(r[s], p);
                }
            }
        }
    }

#pragma unroll
    for (int s = 0; s < E; ++s) {
        int i = t + s * 1024;
        out[(size_t)b * TOPK + i] = __fmul_rn(r[s], scale);
    }
    for (int i = N + t; i < TOPK; i += 1024)
        out[(size_t)b * TOPK + i] = 0.0f;
}

__global__ void __launch_bounds__(1024) k_final(float* __restrict__ out) {
    __shared__ float sm[TOPK];   // 16 KB
    int b = blockIdx.x;

    int K = (int)g_kcnt[b];
    if (K > TOPK) K = TOPK;
    float scale = g_isok[b] ? 1.0f : 0.0f;
    __syncthreads();                              // everyone has read g_kcnt
    if (threadIdx.x == 0) g_kcnt[b] = 0u;         // self-restore for next run

    if (K <= 1024)      sort_desc_emit<1>(out, sm, b, K, scale);
    else if (K <= 2048) sort_desc_emit<2>(out, sm, b, K, scale);
    else                sort_desc_emit<4>(out, sm, b, K, scale);
}

// --------------------------------- launch ----------------------------------
extern "C" void kernel_launch(void* const* d_in, const int* in_sizes, int n_in,
                              void* d_out, int out_size) {
    (void)in_sizes; (void)n_in; (void)out_size;
    const float* det = (const float*)d_in[0];
    float* out = (float*)d_out;

    k_score<<<(BATCH * NDET + RPB - 1) / RPB, TPB>>>(det);  // 128 rows, TMA-staged
    k_nms<<<BATCH * 10, 256>>>(det);                        // 1 warp per (image, class)
    k_final<<<BATCH, 1024>>>(out);
}